// round 3
// baseline (speedup 1.0000x reference)
#include <cuda_runtime.h>
#include <cuda_bf16.h>
#include <cstdint>

// ---------------- problem constants ----------------
#define BATCH 8192
#define INDIM 4096
#define NEXP  8
#define NOUT  4096            // 8 experts * 512
#define KP    12288           // 3 * INDIM  (hi|hi|lo  x  hi|lo|hi split-GEMM)

// ---------------- GEMM tiling ----------------
#define TM 128
#define TN 128
#define TK 64
#define NCHUNK (KP / TK)      // 192
#define STAGES 4
#define PITCH 144             // 64 bf16 = 128B data + 16B pad (conflict-free ldmatrix)
#define A_STAGE_BYTES (TM * PITCH)             // 18432
#define B_STAGE_BYTES (TN * PITCH)             // 18432
#define STAGE_BYTES   (A_STAGE_BYTES + B_STAGE_BYTES)   // 36864
#define SMEM_ALLOC    (STAGES * STAGE_BYTES)   // 147456

// ---------------- scratch ----------------
__device__ __nv_bfloat16 g_A[(size_t)BATCH * KP];   // 192 MiB
__device__ __nv_bfloat16 g_B[(size_t)NOUT  * KP];   //  96 MiB

// ---------------- PTX helpers ----------------
static __device__ __forceinline__ uint32_t smem_u32(const void* p) {
    uint32_t a;
    asm("{ .reg .u64 t; cvta.to.shared.u64 t, %1; cvt.u32.u64 %0, t; }"
        : "=r"(a) : "l"(p));
    return a;
}
static __device__ __forceinline__ void cp16(uint32_t dst, const void* src) {
    asm volatile("cp.async.cg.shared.global [%0], [%1], 16;" :: "r"(dst), "l"(src));
}
static __device__ __forceinline__ void cp_commit() {
    asm volatile("cp.async.commit_group;");
}
static __device__ __forceinline__ void cp_wait2() {
    asm volatile("cp.async.wait_group 2;");
}

static __device__ __forceinline__ void ldsm4(uint32_t& r0, uint32_t& r1,
                                             uint32_t& r2, uint32_t& r3, uint32_t a) {
    asm volatile("ldmatrix.sync.aligned.m8n8.x4.shared.b16 {%0,%1,%2,%3}, [%4];"
                 : "=r"(r0), "=r"(r1), "=r"(r2), "=r"(r3) : "r"(a));
}

static __device__ __forceinline__ void mma_bf16(float* d, const uint32_t* a,
                                                const uint32_t* b) {
    asm volatile(
        "mma.sync.aligned.m16n8k16.row.col.f32.bf16.bf16.f32 "
        "{%0,%1,%2,%3}, {%4,%5,%6,%7}, {%8,%9}, {%0,%1,%2,%3};"
        : "+f"(d[0]), "+f"(d[1]), "+f"(d[2]), "+f"(d[3])
        : "r"(a[0]), "r"(a[1]), "r"(a[2]), "r"(a[3]), "r"(b[0]), "r"(b[1]));
}

// =====================================================================
// prep_x: split x rows into A' = [hi | hi | lo], fused gate + softmax
// =====================================================================
__global__ __launch_bounds__(128) void prep_x_kernel(
    const float* __restrict__ x,
    const float* __restrict__ gw,
    const float* __restrict__ gb,
    const float* __restrict__ adj,
    float* __restrict__ wout)
{
    int b = blockIdx.x;
    int tid = threadIdx.x;
    const float* xr = x + (size_t)b * INDIM;
    __nv_bfloat16* ar = g_A + (size_t)b * KP;

    float acc[NEXP];
    #pragma unroll
    for (int e = 0; e < NEXP; ++e) acc[e] = 0.0f;

    for (int i = tid; i < INDIM; i += 128) {
        float v = __ldg(xr + i);
        __nv_bfloat16 h = __float2bfloat16_rn(v);
        float res = v - __bfloat162float(h);
        __nv_bfloat16 l = __float2bfloat16_rn(res);
        ar[i] = h;
        ar[INDIM + i] = h;
        ar[2 * INDIM + i] = l;
        #pragma unroll
        for (int e = 0; e < NEXP; ++e)
            acc[e] += v * __ldg(gw + (size_t)e * INDIM + i);
    }

    __shared__ float red[NEXP][4];
    int lane = tid & 31, wrp = tid >> 5;
    #pragma unroll
    for (int e = 0; e < NEXP; ++e) {
        float v = acc[e];
        #pragma unroll
        for (int o = 16; o > 0; o >>= 1)
            v += __shfl_xor_sync(0xFFFFFFFFu, v, o);
        if (lane == 0) red[e][wrp] = v;
    }
    __syncthreads();
    if (tid == 0) {
        float lg[NEXP];
        float mx = -1e30f;
        #pragma unroll
        for (int e = 0; e < NEXP; ++e) {
            lg[e] = red[e][0] + red[e][1] + red[e][2] + red[e][3]
                  + __ldg(gb + e) + __ldg(adj + e);
            mx = fmaxf(mx, lg[e]);
        }
        float s = 0.0f;
        #pragma unroll
        for (int e = 0; e < NEXP; ++e) { lg[e] = expf(lg[e] - mx); s += lg[e]; }
        float inv = 1.0f / s;
        #pragma unroll
        for (int e = 0; e < NEXP; ++e)
            wout[(size_t)b * NEXP + e] = lg[e] * inv;
    }
}

// =====================================================================
// prep_w: split Wcat rows into B' = [hi | lo | hi]
// =====================================================================
__global__ __launch_bounds__(128) void prep_w_kernel(const float* __restrict__ W)
{
    int n = blockIdx.x;
    const float* wr = W + (size_t)n * INDIM;
    __nv_bfloat16* br = g_B + (size_t)n * KP;
    for (int i = threadIdx.x; i < INDIM; i += 128) {
        float v = __ldg(wr + i);
        __nv_bfloat16 h = __float2bfloat16_rn(v);
        float res = v - __bfloat162float(h);
        __nv_bfloat16 l = __float2bfloat16_rn(res);
        br[i] = h;
        br[INDIM + i] = l;
        br[2 * INDIM + i] = h;
    }
}

// =====================================================================
// main GEMM: out[m][n] = tanh( sum_k A'[m][k] * B'[n][k] )
// grid: 2048 CTAs (64 m-tiles x 32 n-tiles), 256 threads, mma.sync bf16
// warp layout: 2 (m) x 4 (n); warp tile 64x32
// =====================================================================
__global__ __launch_bounds__(256, 1) void gemm_kernel(float* __restrict__ out)
{
    extern __shared__ __align__(128) char smem[];
    uint32_t sb = smem_u32(smem);
    int tid = threadIdx.x;
    int lane = tid & 31;
    int wid = tid >> 5;

    // panel rasterization: 16 m-tiles per panel (48MB A-panel ~ L2 resident)
    int id = blockIdx.x;
    int panel = id >> 9;                 // / (16*32)
    int mt = panel * 16 + (id & 15);
    int nt = (id >> 4) & 31;
    int m0 = mt * TM;
    int n0 = nt * TN;

    const __nv_bfloat16* Ab = g_A + (size_t)m0 * KP;
    const __nv_bfloat16* Bb = g_B + (size_t)n0 * KP;

    auto load_stage = [&](int c, int s) {
        uint32_t abase = sb + s * STAGE_BYTES;
        uint32_t bbase = abase + A_STAGE_BYTES;
        int k0 = c * TK;
        #pragma unroll
        for (int t = 0; t < 4; ++t) {                 // A: 1024 x 16B
            int i = tid + t * 256;
            int r = i >> 3, cc = i & 7;
            cp16(abase + (uint32_t)r * PITCH + (uint32_t)cc * 16u,
                 Ab + (size_t)r * KP + k0 + cc * 8);
        }
        #pragma unroll
        for (int t = 0; t < 4; ++t) {                 // B: 1024 x 16B
            int i = tid + t * 256;
            int r = i >> 3, cc = i & 7;
            cp16(bbase + (uint32_t)r * PITCH + (uint32_t)cc * 16u,
                 Bb + (size_t)r * KP + k0 + cc * 8);
        }
    };

    // prologue: stages 0..2
    #pragma unroll
    for (int c = 0; c < STAGES - 1; ++c) { load_stage(c, c); cp_commit(); }

    // warp tile origin
    int wm = (wid & 1) * 64;
    int wn = (wid >> 1) * 32;

    // lane-invariant ldmatrix address components
    int a_row  = wm + (lane & 15);
    int a_coff = ((lane >> 4) & 1) * 16;
    int b_row  = wn + (lane & 7) + ((lane >> 4) & 1) * 8;
    int b_coff = ((lane >> 3) & 1) * 16;

    float acc[4][4][4];
    #pragma unroll
    for (int mi = 0; mi < 4; ++mi)
        #pragma unroll
        for (int ni = 0; ni < 4; ++ni)
            #pragma unroll
            for (int j = 0; j < 4; ++j) acc[mi][ni][j] = 0.0f;

    for (int c = 0; c < NCHUNK; ++c) {
        cp_wait2();
        __syncthreads();

        int ld = c + STAGES - 1;
        if (ld < NCHUNK) load_stage(ld, ld & 3);
        cp_commit();

        uint32_t abase = sb + (c & 3) * STAGE_BYTES;
        uint32_t bbase = abase + A_STAGE_BYTES;

        #pragma unroll
        for (int ks = 0; ks < 4; ++ks) {
            uint32_t af[4][4];
            uint32_t bf[4][2];
            #pragma unroll
            for (int mi = 0; mi < 4; ++mi)
                ldsm4(af[mi][0], af[mi][1], af[mi][2], af[mi][3],
                      abase + (uint32_t)(a_row + mi * 16) * PITCH + ks * 32 + a_coff);
            #pragma unroll
            for (int j = 0; j < 2; ++j)
                ldsm4(bf[2 * j][0], bf[2 * j][1], bf[2 * j + 1][0], bf[2 * j + 1][1],
                      bbase + (uint32_t)(b_row + j * 16) * PITCH + ks * 32 + b_coff);
            #pragma unroll
            for (int mi = 0; mi < 4; ++mi)
                #pragma unroll
                for (int ni = 0; ni < 4; ++ni)
                    mma_bf16(acc[mi][ni], af[mi], bf[ni]);
        }
    }

    // ---------------- epilogue: tanh + store ----------------
    #pragma unroll
    for (int mi = 0; mi < 4; ++mi) {
        #pragma unroll
        for (int ni = 0; ni < 4; ++ni) {
            int r = m0 + wm + mi * 16 + (lane >> 2);
            int c = n0 + wn + ni * 8 + (lane & 3) * 2;
            float t0, t1, t2, t3;
            asm("tanh.approx.f32 %0, %1;" : "=f"(t0) : "f"(acc[mi][ni][0]));
            asm("tanh.approx.f32 %0, %1;" : "=f"(t1) : "f"(acc[mi][ni][1]));
            asm("tanh.approx.f32 %0, %1;" : "=f"(t2) : "f"(acc[mi][ni][2]));
            asm("tanh.approx.f32 %0, %1;" : "=f"(t3) : "f"(acc[mi][ni][3]));
            *reinterpret_cast<float2*>(out + (size_t)r * NOUT + c) =
                make_float2(t0, t1);
            *reinterpret_cast<float2*>(out + (size_t)(r + 8) * NOUT + c) =
                make_float2(t2, t3);
        }
    }
}

// =====================================================================
extern "C" void kernel_launch(void* const* d_in, const int* in_sizes, int n_in,
                              void* d_out, int out_size)
{
    const float* x   = (const float*)d_in[0];
    const float* W   = (const float*)d_in[1];
    const float* gw  = (const float*)d_in[2];
    const float* gb  = (const float*)d_in[3];
    const float* adj = (const float*)d_in[4];

    float* out  = (float*)d_out;
    float* wout = out + (size_t)BATCH * NOUT;

    cudaFuncSetAttribute(gemm_kernel,
                         cudaFuncAttributeMaxDynamicSharedMemorySize, SMEM_ALLOC);

    prep_x_kernel<<<BATCH, 128>>>(x, gw, gb, adj, wout);
    prep_w_kernel<<<NOUT, 128>>>(W);
    gemm_kernel<<<2048, 256, SMEM_ALLOC>>>(out);
}

// round 5
// speedup vs baseline: 1.5565x; 1.5565x over previous
#include <cuda_runtime.h>
#include <cuda_fp16.h>
#include <cstdint>

// ---------------- problem constants ----------------
#define BATCH 8192
#define INDIM 4096
#define NEXP  8
#define NOUT  4096            // 8 experts * 512

// ---------------- GEMM tiling ----------------
#define TM 128
#define TN 128
#define NCH 64                // chunks per phase (each chunk = 128 bytes of K per row)
#define ROWB 8192             // bytes per K-row in both phases (4096 fp16 / 8192 int8)
#define STAGES 4
#define PITCH 144             // 128B data + 16B pad (conflict-free ldmatrix)
#define A_STAGE_BYTES (TM * PITCH)             // 18432
#define STAGE_BYTES   (2 * TM * PITCH)         // 36864
#define SMEM_ALLOC    (STAGES * STAGE_BYTES)   // 147456

#define INV_S (1.0f / 524288.0f)   // 2^-19 = 1/(16 * 32768)

// ---------------- scratch ----------------
__device__ __half       g_A16[(size_t)BATCH * INDIM];   // 64 MiB
__device__ __half       g_B16[(size_t)NOUT  * INDIM];   // 32 MiB
__device__ signed char  g_A8 [(size_t)BATCH * 2 * INDIM]; // 64 MiB  [h_q | l_q]
__device__ signed char  g_B8 [(size_t)NOUT  * 2 * INDIM]; // 32 MiB  [l_q | h_q]

// ---------------- PTX helpers ----------------
static __device__ __forceinline__ uint32_t smem_u32(const void* p) {
    uint32_t a;
    asm("{ .reg .u64 t; cvta.to.shared.u64 t, %1; cvt.u32.u64 %0, t; }"
        : "=r"(a) : "l"(p));
    return a;
}
static __device__ __forceinline__ void cp16(uint32_t dst, const void* src) {
    asm volatile("cp.async.cg.shared.global [%0], [%1], 16;" :: "r"(dst), "l"(src));
}
static __device__ __forceinline__ void cp_commit() {
    asm volatile("cp.async.commit_group;");
}
static __device__ __forceinline__ void cp_wait2() {
    asm volatile("cp.async.wait_group 2;");
}

static __device__ __forceinline__ void ldsm4(uint32_t& r0, uint32_t& r1,
                                             uint32_t& r2, uint32_t& r3, uint32_t a) {
    asm volatile("ldmatrix.sync.aligned.m8n8.x4.shared.b16 {%0,%1,%2,%3}, [%4];"
                 : "=r"(r0), "=r"(r1), "=r"(r2), "=r"(r3) : "r"(a));
}

static __device__ __forceinline__ void mma_f16(float* d, const uint32_t* a,
                                               const uint32_t* b) {
    asm volatile(
        "mma.sync.aligned.m16n8k16.row.col.f32.f16.f16.f32 "
        "{%0,%1,%2,%3}, {%4,%5,%6,%7}, {%8,%9}, {%0,%1,%2,%3};"
        : "+f"(d[0]), "+f"(d[1]), "+f"(d[2]), "+f"(d[3])
        : "r"(a[0]), "r"(a[1]), "r"(a[2]), "r"(a[3]), "r"(b[0]), "r"(b[1]));
}
static __device__ __forceinline__ void mma_s8(int* d, const uint32_t* a,
                                              const uint32_t* b) {
    asm volatile(
        "mma.sync.aligned.m16n8k32.row.col.s32.s8.s8.s32 "
        "{%0,%1,%2,%3}, {%4,%5,%6,%7}, {%8,%9}, {%0,%1,%2,%3};"
        : "+r"(d[0]), "+r"(d[1]), "+r"(d[2]), "+r"(d[3])
        : "r"(a[0]), "r"(a[1]), "r"(a[2]), "r"(a[3]), "r"(b[0]), "r"(b[1]));
}

static __device__ __forceinline__ signed char q8(float v) {
    int q = __float2int_rn(v);
    q = max(-127, min(127, q));
    return (signed char)q;
}

// =====================================================================
// prep_x: h=fp16(v) -> A16; [rnd(16h) | rnd(2^15 l)] -> A8; fused gate
// =====================================================================
__global__ __launch_bounds__(128) void prep_x_kernel(
    const float* __restrict__ x,
    const float* __restrict__ gw,
    const float* __restrict__ gb,
    const float* __restrict__ adj,
    float* __restrict__ wout)
{
    int b = blockIdx.x;
    int tid = threadIdx.x;
    const float4* xr = (const float4*)(x + (size_t)b * INDIM);
    __half2* a16 = (__half2*)(g_A16 + (size_t)b * INDIM);
    char4* a8h = (char4*)(g_A8 + (size_t)b * 2 * INDIM);
    char4* a8l = (char4*)(g_A8 + (size_t)b * 2 * INDIM + INDIM);

    float acc[NEXP];
    #pragma unroll
    for (int e = 0; e < NEXP; ++e) acc[e] = 0.0f;

    #pragma unroll
    for (int it = 0; it < 8; ++it) {
        int i4 = tid + it * 128;              // float4 index [0,1024)
        float4 v = __ldg(xr + i4);
        __half h0 = __float2half_rn(v.x), h1 = __float2half_rn(v.y);
        __half h2 = __float2half_rn(v.z), h3 = __float2half_rn(v.w);
        float f0 = __half2float(h0), f1 = __half2float(h1);
        float f2 = __half2float(h2), f3 = __half2float(h3);
        a16[i4 * 2]     = __halves2half2(h0, h1);
        a16[i4 * 2 + 1] = __halves2half2(h2, h3);
        a8h[i4] = make_char4(q8(f0 * 16.f), q8(f1 * 16.f),
                             q8(f2 * 16.f), q8(f3 * 16.f));
        a8l[i4] = make_char4(q8((v.x - f0) * 32768.f), q8((v.y - f1) * 32768.f),
                             q8((v.z - f2) * 32768.f), q8((v.w - f3) * 32768.f));
        #pragma unroll
        for (int e = 0; e < NEXP; ++e) {
            float4 g = __ldg((const float4*)(gw + (size_t)e * INDIM) + i4);
            acc[e] += v.x * g.x + v.y * g.y + v.z * g.z + v.w * g.w;
        }
    }

    __shared__ float red[NEXP][4];
    int lane = tid & 31, wrp = tid >> 5;
    #pragma unroll
    for (int e = 0; e < NEXP; ++e) {
        float v = acc[e];
        #pragma unroll
        for (int o = 16; o > 0; o >>= 1)
            v += __shfl_xor_sync(0xFFFFFFFFu, v, o);
        if (lane == 0) red[e][wrp] = v;
    }
    __syncthreads();
    if (tid == 0) {
        float lg[NEXP];
        float mx = -1e30f;
        #pragma unroll
        for (int e = 0; e < NEXP; ++e) {
            lg[e] = red[e][0] + red[e][1] + red[e][2] + red[e][3]
                  + __ldg(gb + e) + __ldg(adj + e);
            mx = fmaxf(mx, lg[e]);
        }
        float s = 0.0f;
        #pragma unroll
        for (int e = 0; e < NEXP; ++e) { lg[e] = expf(lg[e] - mx); s += lg[e]; }
        float inv = 1.0f / s;
        #pragma unroll
        for (int e = 0; e < NEXP; ++e)
            wout[(size_t)b * NEXP + e] = lg[e] * inv;
    }
}

// =====================================================================
// prep_w: h=fp16(v) -> B16; [rnd(2^15 l) | rnd(16h)] -> B8
// =====================================================================
__global__ __launch_bounds__(128) void prep_w_kernel(const float* __restrict__ W)
{
    int n = blockIdx.x;
    const float4* wr = (const float4*)(W + (size_t)n * INDIM);
    __half2* b16 = (__half2*)(g_B16 + (size_t)n * INDIM);
    char4* b8l = (char4*)(g_B8 + (size_t)n * 2 * INDIM);
    char4* b8h = (char4*)(g_B8 + (size_t)n * 2 * INDIM + INDIM);

    #pragma unroll
    for (int it = 0; it < 8; ++it) {
        int i4 = threadIdx.x + it * 128;
        float4 v = __ldg(wr + i4);
        __half h0 = __float2half_rn(v.x), h1 = __float2half_rn(v.y);
        __half h2 = __float2half_rn(v.z), h3 = __float2half_rn(v.w);
        float f0 = __half2float(h0), f1 = __half2float(h1);
        float f2 = __half2float(h2), f3 = __half2float(h3);
        b16[i4 * 2]     = __halves2half2(h0, h1);
        b16[i4 * 2 + 1] = __halves2half2(h2, h3);
        b8h[i4] = make_char4(q8(f0 * 16.f), q8(f1 * 16.f),
                             q8(f2 * 16.f), q8(f3 * 16.f));
        b8l[i4] = make_char4(q8((v.x - f0) * 32768.f), q8((v.y - f1) * 32768.f),
                             q8((v.z - f2) * 32768.f), q8((v.w - f3) * 32768.f));
    }
}

// =====================================================================
// main GEMM: out = tanh( A16·B16^T + 2^-19 * A8·B8^T )
// grid: 2048 CTAs (64 m-tiles x 32 n-tiles), 256 threads
// phase1: fp16 m16n8k16 (64 chunks); phase2: int8 m16n8k32 (64 chunks)
// =====================================================================
__global__ __launch_bounds__(256, 1) void gemm_kernel(float* __restrict__ out)
{
    extern __shared__ __align__(128) char smem[];
    uint32_t sb = smem_u32(smem);
    int tid = threadIdx.x;
    int lane = tid & 31;
    int wid = tid >> 5;

    // panel rasterization: 16 m-tiles per panel
    int id = blockIdx.x;
    int panel = id >> 9;
    int mt = panel * 16 + (id & 15);
    int nt = (id >> 4) & 31;
    int m0 = mt * TM;
    int n0 = nt * TN;

    const char* A16p = (const char*)g_A16 + (size_t)m0 * ROWB;
    const char* B16p = (const char*)g_B16 + (size_t)n0 * ROWB;
    const char* A8p  = (const char*)g_A8  + (size_t)m0 * ROWB;
    const char* B8p  = (const char*)g_B8  + (size_t)n0 * ROWB;

    // both phases: 128 rows A + 128 rows B, 128B per row per chunk
    auto load_stage = [&](const char* Ag, const char* Bg, int c, int s) {
        uint32_t abase = sb + s * STAGE_BYTES;
        uint32_t bbase = abase + A_STAGE_BYTES;
        size_t k0 = (size_t)c * 128;
        #pragma unroll
        for (int t = 0; t < 4; ++t) {
            int i = tid + t * 256;
            int r = i >> 3, cc = i & 7;
            cp16(abase + (uint32_t)r * PITCH + (uint32_t)cc * 16u,
                 Ag + (size_t)r * ROWB + k0 + cc * 16);
        }
        #pragma unroll
        for (int t = 0; t < 4; ++t) {
            int i = tid + t * 256;
            int r = i >> 3, cc = i & 7;
            cp16(bbase + (uint32_t)r * PITCH + (uint32_t)cc * 16u,
                 Bg + (size_t)r * ROWB + k0 + cc * 16);
        }
    };

    // warp tile origin: 2 (m) x 4 (n) warps, warp tile 64x32
    int wm = (wid & 1) * 64;
    int wn = (wid >> 1) * 32;
    int a_row  = wm + (lane & 15);
    int a_coff = ((lane >> 4) & 1) * 16;
    int b_row  = wn + (lane & 7) + ((lane >> 4) & 1) * 8;
    int b_coff = ((lane >> 3) & 1) * 16;

    float accf[4][4][4];
    int   acci[4][4][4];
    #pragma unroll
    for (int mi = 0; mi < 4; ++mi)
        #pragma unroll
        for (int ni = 0; ni < 4; ++ni)
            #pragma unroll
            for (int j = 0; j < 4; ++j) { accf[mi][ni][j] = 0.0f; acci[mi][ni][j] = 0; }

    // -------- phase 1: fp16 --------
    #pragma unroll
    for (int c = 0; c < STAGES - 1; ++c) { load_stage(A16p, B16p, c, c); cp_commit(); }

    for (int c = 0; c < NCH; ++c) {
        cp_wait2();
        __syncthreads();

        int ld = c + STAGES - 1;
        if (ld < NCH) load_stage(A16p, B16p, ld, ld & 3);
        cp_commit();

        uint32_t abase = sb + (c & 3) * STAGE_BYTES;
        uint32_t bbase = abase + A_STAGE_BYTES;
        #pragma unroll
        for (int ks = 0; ks < 4; ++ks) {
            uint32_t af[4][4], bf[4][2];
            #pragma unroll
            for (int mi = 0; mi < 4; ++mi)
                ldsm4(af[mi][0], af[mi][1], af[mi][2], af[mi][3],
                      abase + (uint32_t)(a_row + mi * 16) * PITCH + ks * 32 + a_coff);
            #pragma unroll
            for (int j = 0; j < 2; ++j)
                ldsm4(bf[2 * j][0], bf[2 * j][1], bf[2 * j + 1][0], bf[2 * j + 1][1],
                      bbase + (uint32_t)(b_row + j * 16) * PITCH + ks * 32 + b_coff);
            #pragma unroll
            for (int mi = 0; mi < 4; ++mi)
                #pragma unroll
                for (int ni = 0; ni < 4; ++ni)
                    mma_f16(accf[mi][ni], af[mi], bf[ni]);
        }
    }
    __syncthreads();

    // -------- phase 2: int8 (cross terms, scale 2^19) --------
    #pragma unroll
    for (int c = 0; c < STAGES - 1; ++c) { load_stage(A8p, B8p, c, c); cp_commit(); }

    for (int c = 0; c < NCH; ++c) {
        cp_wait2();
        __syncthreads();

        int ld = c + STAGES - 1;
        if (ld < NCH) load_stage(A8p, B8p, ld, ld & 3);
        cp_commit();

        uint32_t abase = sb + (c & 3) * STAGE_BYTES;
        uint32_t bbase = abase + A_STAGE_BYTES;
        #pragma unroll
        for (int ks = 0; ks < 4; ++ks) {
            uint32_t af[4][4], bf[4][2];
            #pragma unroll
            for (int mi = 0; mi < 4; ++mi)
                ldsm4(af[mi][0], af[mi][1], af[mi][2], af[mi][3],
                      abase + (uint32_t)(a_row + mi * 16) * PITCH + ks * 32 + a_coff);
            #pragma unroll
            for (int j = 0; j < 2; ++j)
                ldsm4(bf[2 * j][0], bf[2 * j][1], bf[2 * j + 1][0], bf[2 * j + 1][1],
                      bbase + (uint32_t)(b_row + j * 16) * PITCH + ks * 32 + b_coff);
            #pragma unroll
            for (int mi = 0; mi < 4; ++mi)
                #pragma unroll
                for (int ni = 0; ni < 4; ++ni)
                    mma_s8(acci[mi][ni], af[mi], bf[ni]);
        }
    }

    // ---------------- epilogue: combine + tanh + store ----------------
    #pragma unroll
    for (int mi = 0; mi < 4; ++mi) {
        #pragma unroll
        for (int ni = 0; ni < 4; ++ni) {
            int r = m0 + wm + mi * 16 + (lane >> 2);
            int c = n0 + wn + ni * 8 + (lane & 3) * 2;
            float v0 = accf[mi][ni][0] + (float)acci[mi][ni][0] * INV_S;
            float v1 = accf[mi][ni][1] + (float)acci[mi][ni][1] * INV_S;
            float v2 = accf[mi][ni][2] + (float)acci[mi][ni][2] * INV_S;
            float v3 = accf[mi][ni][3] + (float)acci[mi][ni][3] * INV_S;
            float t0, t1, t2, t3;
            asm("tanh.approx.f32 %0, %1;" : "=f"(t0) : "f"(v0));
            asm("tanh.approx.f32 %0, %1;" : "=f"(t1) : "f"(v1));
            asm("tanh.approx.f32 %0, %1;" : "=f"(t2) : "f"(v2));
            asm("tanh.approx.f32 %0, %1;" : "=f"(t3) : "f"(v3));
            *reinterpret_cast<float2*>(out + (size_t)r * NOUT + c) =
                make_float2(t0, t1);
            *reinterpret_cast<float2*>(out + (size_t)(r + 8) * NOUT + c) =
                make_float2(t2, t3);
        }
    }
}

// =====================================================================
extern "C" void kernel_launch(void* const* d_in, const int* in_sizes, int n_in,
                              void* d_out, int out_size)
{
    const float* x   = (const float*)d_in[0];
    const float* W   = (const float*)d_in[1];
    const float* gw  = (const float*)d_in[2];
    const float* gb  = (const float*)d_in[3];
    const float* adj = (const float*)d_in[4];

    float* out  = (float*)d_out;
    float* wout = out + (size_t)BATCH * NOUT;

    cudaFuncSetAttribute(gemm_kernel,
                         cudaFuncAttributeMaxDynamicSharedMemorySize, SMEM_ALLOC);

    prep_x_kernel<<<BATCH, 128>>>(x, gw, gb, adj, wout);
    prep_w_kernel<<<NOUT, 128>>>(W);
    gemm_kernel<<<2048, 256, SMEM_ALLOC>>>(out);
}

// round 6
// speedup vs baseline: 2.0792x; 1.3358x over previous
#include <cuda_runtime.h>
#include <cuda_fp16.h>
#include <cstdint>

// ---------------- problem constants ----------------
#define BATCH 8192
#define INDIM 4096
#define NEXP  8
#define NOUT  4096            // 8 experts * 512

// ---------------- GEMM tiling ----------------
#define TM 128
#define TN 128
#define NCH 32                // chunks per phase (each chunk = 128 bytes of K per row)
#define ROWB 8192             // bytes per K-row: [digit_a (4096) | digit_b (4096)]
#define STAGES 4
#define PITCH 144             // 128B data + 16B pad (conflict-free ldmatrix)
#define A_STAGE_BYTES (TM * PITCH)             // 18432
#define STAGE_BYTES   (2 * TM * PITCH)         // 36864
#define SMEM_ALLOC    (STAGES * STAGE_BYTES)   // 147456

#define DIG2 254.0f
#define INV_DIG2 (1.0f / 254.0f)

// ---------------- scratch ----------------
__device__ signed char g_A8[(size_t)BATCH * ROWB];  // 64 MiB  [a | b]
__device__ signed char g_B8[(size_t)NOUT  * ROWB];  // 32 MiB  [c | d]
__device__ float       g_px[BATCH];                 // per-row scale of x
__device__ float       g_qw[NOUT];                  // per-row scale of W

// ---------------- PTX helpers ----------------
static __device__ __forceinline__ uint32_t smem_u32(const void* p) {
    uint32_t a;
    asm("{ .reg .u64 t; cvta.to.shared.u64 t, %1; cvt.u32.u64 %0, t; }"
        : "=r"(a) : "l"(p));
    return a;
}
static __device__ __forceinline__ void cp16(uint32_t dst, const void* src) {
    asm volatile("cp.async.cg.shared.global [%0], [%1], 16;" :: "r"(dst), "l"(src));
}
static __device__ __forceinline__ void cp_commit() {
    asm volatile("cp.async.commit_group;");
}
static __device__ __forceinline__ void cp_wait2() {
    asm volatile("cp.async.wait_group 2;");
}

static __device__ __forceinline__ void ldsm4(uint32_t& r0, uint32_t& r1,
                                             uint32_t& r2, uint32_t& r3, uint32_t a) {
    asm volatile("ldmatrix.sync.aligned.m8n8.x4.shared.b16 {%0,%1,%2,%3}, [%4];"
                 : "=r"(r0), "=r"(r1), "=r"(r2), "=r"(r3) : "r"(a));
}

static __device__ __forceinline__ void mma_s8(int* d, const uint32_t* a,
                                              const uint32_t* b) {
    asm volatile(
        "mma.sync.aligned.m16n8k32.row.col.s32.s8.s8.s32 "
        "{%0,%1,%2,%3}, {%4,%5,%6,%7}, {%8,%9}, {%0,%1,%2,%3};"
        : "+r"(d[0]), "+r"(d[1]), "+r"(d[2]), "+r"(d[3])
        : "r"(a[0]), "r"(a[1]), "r"(a[2]), "r"(a[3]), "r"(b[0]), "r"(b[1]));
}

static __device__ __forceinline__ int q8i(float v) {
    int q = __float2int_rn(v);
    return max(-127, min(127, q));
}

// =====================================================================
// 2-digit int8 row quantization: v = (a + b/254) * p, p = rowmax/127
// =====================================================================

// prep_x: quantize x rows -> g_A8 [a|b], scale -> g_px; fused gate+softmax
__global__ __launch_bounds__(128) void prep_x_kernel(
    const float* __restrict__ x,
    const float* __restrict__ gw,
    const float* __restrict__ gb,
    const float* __restrict__ adj,
    float* __restrict__ wout)
{
    int b = blockIdx.x;
    int tid = threadIdx.x;
    const float4* xr = (const float4*)(x + (size_t)b * INDIM);
    char4* a8 = (char4*)(g_A8 + (size_t)b * ROWB);
    char4* b8 = (char4*)(g_A8 + (size_t)b * ROWB + INDIM);

    float4 v[8];
    float mx = 0.0f;
    float acc[NEXP];
    #pragma unroll
    for (int e = 0; e < NEXP; ++e) acc[e] = 0.0f;

    #pragma unroll
    for (int it = 0; it < 8; ++it) {
        int i4 = tid + it * 128;
        v[it] = __ldg(xr + i4);
        mx = fmaxf(mx, fmaxf(fmaxf(fabsf(v[it].x), fabsf(v[it].y)),
                             fmaxf(fabsf(v[it].z), fabsf(v[it].w))));
        #pragma unroll
        for (int e = 0; e < NEXP; ++e) {
            float4 g = __ldg((const float4*)(gw + (size_t)e * INDIM) + i4);
            acc[e] += v[it].x * g.x + v[it].y * g.y + v[it].z * g.z + v[it].w * g.w;
        }
    }

    // block max reduction
    __shared__ float wmax[4];
    __shared__ float red[NEXP][4];
    int lane = tid & 31, wrp = tid >> 5;
    #pragma unroll
    for (int o = 16; o > 0; o >>= 1)
        mx = fmaxf(mx, __shfl_xor_sync(0xFFFFFFFFu, mx, o));
    if (lane == 0) wmax[wrp] = mx;

    #pragma unroll
    for (int e = 0; e < NEXP; ++e) {
        float s = acc[e];
        #pragma unroll
        for (int o = 16; o > 0; o >>= 1)
            s += __shfl_xor_sync(0xFFFFFFFFu, s, o);
        if (lane == 0) red[e][wrp] = s;
    }
    __syncthreads();
    mx = fmaxf(fmaxf(wmax[0], wmax[1]), fmaxf(wmax[2], wmax[3]));
    mx = fmaxf(mx, 1e-30f);
    float p = mx * (1.0f / 127.0f);
    float invp = 127.0f / mx;
    if (tid == 0) g_px[b] = p;

    #pragma unroll
    for (int it = 0; it < 8; ++it) {
        int i4 = tid + it * 128;
        int a0 = q8i(v[it].x * invp), a1 = q8i(v[it].y * invp);
        int a2 = q8i(v[it].z * invp), a3 = q8i(v[it].w * invp);
        float r0 = fmaf(-(float)a0, p, v[it].x);
        float r1 = fmaf(-(float)a1, p, v[it].y);
        float r2 = fmaf(-(float)a2, p, v[it].z);
        float r3 = fmaf(-(float)a3, p, v[it].w);
        float s2 = DIG2 * invp;
        a8[i4] = make_char4((signed char)a0, (signed char)a1,
                            (signed char)a2, (signed char)a3);
        b8[i4] = make_char4((signed char)q8i(r0 * s2), (signed char)q8i(r1 * s2),
                            (signed char)q8i(r2 * s2), (signed char)q8i(r3 * s2));
    }

    if (tid == 0) {
        float lg[NEXP];
        float m2 = -1e30f;
        #pragma unroll
        for (int e = 0; e < NEXP; ++e) {
            lg[e] = red[e][0] + red[e][1] + red[e][2] + red[e][3]
                  + __ldg(gb + e) + __ldg(adj + e);
            m2 = fmaxf(m2, lg[e]);
        }
        float s = 0.0f;
        #pragma unroll
        for (int e = 0; e < NEXP; ++e) { lg[e] = expf(lg[e] - m2); s += lg[e]; }
        float inv = 1.0f / s;
        #pragma unroll
        for (int e = 0; e < NEXP; ++e)
            wout[(size_t)b * NEXP + e] = lg[e] * inv;
    }
}

// prep_w: quantize W rows -> g_B8 [c|d], scale -> g_qw
__global__ __launch_bounds__(128) void prep_w_kernel(const float* __restrict__ W)
{
    int n = blockIdx.x;
    int tid = threadIdx.x;
    const float4* wr = (const float4*)(W + (size_t)n * INDIM);
    char4* c8 = (char4*)(g_B8 + (size_t)n * ROWB);
    char4* d8 = (char4*)(g_B8 + (size_t)n * ROWB + INDIM);

    float4 v[8];
    float mx = 0.0f;
    #pragma unroll
    for (int it = 0; it < 8; ++it) {
        int i4 = tid + it * 128;
        v[it] = __ldg(wr + i4);
        mx = fmaxf(mx, fmaxf(fmaxf(fabsf(v[it].x), fabsf(v[it].y)),
                             fmaxf(fabsf(v[it].z), fabsf(v[it].w))));
    }

    __shared__ float wmax[4];
    int lane = tid & 31, wrp = tid >> 5;
    #pragma unroll
    for (int o = 16; o > 0; o >>= 1)
        mx = fmaxf(mx, __shfl_xor_sync(0xFFFFFFFFu, mx, o));
    if (lane == 0) wmax[wrp] = mx;
    __syncthreads();
    mx = fmaxf(fmaxf(wmax[0], wmax[1]), fmaxf(wmax[2], wmax[3]));
    mx = fmaxf(mx, 1e-30f);
    float p = mx * (1.0f / 127.0f);
    float invp = 127.0f / mx;
    if (tid == 0) g_qw[n] = p;

    #pragma unroll
    for (int it = 0; it < 8; ++it) {
        int i4 = tid + it * 128;
        int a0 = q8i(v[it].x * invp), a1 = q8i(v[it].y * invp);
        int a2 = q8i(v[it].z * invp), a3 = q8i(v[it].w * invp);
        float r0 = fmaf(-(float)a0, p, v[it].x);
        float r1 = fmaf(-(float)a1, p, v[it].y);
        float r2 = fmaf(-(float)a2, p, v[it].z);
        float r3 = fmaf(-(float)a3, p, v[it].w);
        float s2 = DIG2 * invp;
        c8[i4] = make_char4((signed char)a0, (signed char)a1,
                            (signed char)a2, (signed char)a3);
        d8[i4] = make_char4((signed char)q8i(r0 * s2), (signed char)q8i(r1 * s2),
                            (signed char)q8i(r2 * s2), (signed char)q8i(r3 * s2));
    }
}

// =====================================================================
// main GEMM: out = tanh( (a·c + (b·c + a·d)/254) * px[m] * qw[n] )
// 3 int8 phases of 32 chunks each; grid 2048 CTAs, 256 threads
// =====================================================================
__global__ __launch_bounds__(256, 1) void gemm_kernel(float* __restrict__ out)
{
    extern __shared__ __align__(128) char smem[];
    uint32_t sb = smem_u32(smem);
    int tid = threadIdx.x;
    int lane = tid & 31;
    int wid = tid >> 5;

    // panel rasterization: 16 m-tiles per panel
    int id = blockIdx.x;
    int panel = id >> 9;
    int mt = panel * 16 + (id & 15);
    int nt = (id >> 4) & 31;
    int m0 = mt * TM;
    int n0 = nt * TN;

    const char* Abase = (const char*)g_A8 + (size_t)m0 * ROWB;
    const char* Bbase = (const char*)g_B8 + (size_t)n0 * ROWB;

    auto load_stage = [&](const char* Ag, const char* Bg, int c, int s) {
        uint32_t abase = sb + s * STAGE_BYTES;
        uint32_t bbase = abase + A_STAGE_BYTES;
        size_t k0 = (size_t)c * 128;
        #pragma unroll
        for (int t = 0; t < 4; ++t) {
            int i = tid + t * 256;
            int r = i >> 3, cc = i & 7;
            cp16(abase + (uint32_t)r * PITCH + (uint32_t)cc * 16u,
                 Ag + (size_t)r * ROWB + k0 + cc * 16);
        }
        #pragma unroll
        for (int t = 0; t < 4; ++t) {
            int i = tid + t * 256;
            int r = i >> 3, cc = i & 7;
            cp16(bbase + (uint32_t)r * PITCH + (uint32_t)cc * 16u,
                 Bg + (size_t)r * ROWB + k0 + cc * 16);
        }
    };

    // warp tile origin: 2 (m) x 4 (n) warps, warp tile 64x32
    int wm = (wid & 1) * 64;
    int wn = (wid >> 1) * 32;
    int a_row  = wm + (lane & 15);
    int a_coff = ((lane >> 4) & 1) * 16;
    int b_row  = wn + (lane & 7) + ((lane >> 4) & 1) * 8;
    int b_coff = ((lane >> 3) & 1) * 16;

    int acc1[4][4][4];   // a·c
    int acc2[4][4][4];   // b·c + a·d
    #pragma unroll
    for (int mi = 0; mi < 4; ++mi)
        #pragma unroll
        for (int ni = 0; ni < 4; ++ni)
            #pragma unroll
            for (int j = 0; j < 4; ++j) { acc1[mi][ni][j] = 0; acc2[mi][ni][j] = 0; }

    auto run_phase = [&](const char* Ag, const char* Bg, int (&acc)[4][4][4]) {
        #pragma unroll
        for (int c = 0; c < STAGES - 1; ++c) { load_stage(Ag, Bg, c, c); cp_commit(); }

        for (int c = 0; c < NCH; ++c) {
            cp_wait2();
            __syncthreads();

            int ld = c + STAGES - 1;
            if (ld < NCH) load_stage(Ag, Bg, ld, ld & 3);
            cp_commit();

            uint32_t abase = sb + (c & 3) * STAGE_BYTES;
            uint32_t bbase = abase + A_STAGE_BYTES;
            #pragma unroll
            for (int ks = 0; ks < 4; ++ks) {
                uint32_t af[4][4], bf[4][2];
                #pragma unroll
                for (int mi = 0; mi < 4; ++mi)
                    ldsm4(af[mi][0], af[mi][1], af[mi][2], af[mi][3],
                          abase + (uint32_t)(a_row + mi * 16) * PITCH + ks * 32 + a_coff);
                #pragma unroll
                for (int j = 0; j < 2; ++j)
                    ldsm4(bf[2 * j][0], bf[2 * j][1], bf[2 * j + 1][0], bf[2 * j + 1][1],
                          bbase + (uint32_t)(b_row + j * 16) * PITCH + ks * 32 + b_coff);
                #pragma unroll
                for (int mi = 0; mi < 4; ++mi)
                    #pragma unroll
                    for (int ni = 0; ni < 4; ++ni)
                        mma_s8(acc[mi][ni], af[mi], bf[ni]);
            }
        }
        __syncthreads();
    };

    run_phase(Abase,         Bbase,         acc1);  // a · c
    run_phase(Abase + INDIM, Bbase,         acc2);  // b · c
    run_phase(Abase,         Bbase + INDIM, acc2);  // a · d

    // ---------------- epilogue: scale + tanh + store ----------------
    #pragma unroll
    for (int mi = 0; mi < 4; ++mi) {
        int r = m0 + wm + mi * 16 + (lane >> 2);
        float pm0 = __ldg(g_px + r);
        float pm1 = __ldg(g_px + r + 8);
        #pragma unroll
        for (int ni = 0; ni < 4; ++ni) {
            int c = n0 + wn + ni * 8 + (lane & 3) * 2;
            float qn0 = __ldg(g_qw + c);
            float qn1 = __ldg(g_qw + c + 1);
            float v0 = ((float)acc1[mi][ni][0] + (float)acc2[mi][ni][0] * INV_DIG2) * pm0 * qn0;
            float v1 = ((float)acc1[mi][ni][1] + (float)acc2[mi][ni][1] * INV_DIG2) * pm0 * qn1;
            float v2 = ((float)acc1[mi][ni][2] + (float)acc2[mi][ni][2] * INV_DIG2) * pm1 * qn0;
            float v3 = ((float)acc1[mi][ni][3] + (float)acc2[mi][ni][3] * INV_DIG2) * pm1 * qn1;
            float t0, t1, t2, t3;
            asm("tanh.approx.f32 %0, %1;" : "=f"(t0) : "f"(v0));
            asm("tanh.approx.f32 %0, %1;" : "=f"(t1) : "f"(v1));
            asm("tanh.approx.f32 %0, %1;" : "=f"(t2) : "f"(v2));
            asm("tanh.approx.f32 %0, %1;" : "=f"(t3) : "f"(v3));
            *reinterpret_cast<float2*>(out + (size_t)r * NOUT + c) =
                make_float2(t0, t1);
            *reinterpret_cast<float2*>(out + (size_t)(r + 8) * NOUT + c) =
                make_float2(t2, t3);
        }
    }
}

// =====================================================================
extern "C" void kernel_launch(void* const* d_in, const int* in_sizes, int n_in,
                              void* d_out, int out_size)
{
    const float* x   = (const float*)d_in[0];
    const float* W   = (const float*)d_in[1];
    const float* gw  = (const float*)d_in[2];
    const float* gb  = (const float*)d_in[3];
    const float* adj = (const float*)d_in[4];

    float* out  = (float*)d_out;
    float* wout = out + (size_t)BATCH * NOUT;

    cudaFuncSetAttribute(gemm_kernel,
                         cudaFuncAttributeMaxDynamicSharedMemorySize, SMEM_ALLOC);

    prep_x_kernel<<<BATCH, 128>>>(x, gw, gb, adj, wout);
    prep_w_kernel<<<NOUT, 128>>>(W);
    gemm_kernel<<<2048, 256, SMEM_ALLOC>>>(out);
}